// round 8
// baseline (speedup 1.0000x reference)
#include <cuda_runtime.h>
#include <cuda_fp16.h>
#include <cuda_bf16.h>
#include <cstdint>

#define M_TOT 256
#define N_TOT 16384
#define K_TOT 4096
#define G_TOT (N_TOT * K_TOT / 16)   // 4194304
#define GPR   (K_TOT / 16)           // 256 groups per row

#define M_TILE 128
#define N_TILE 64
#define K_CHUNK 64
#define NCHUNK (K_TOT / K_CHUNK)     // 64
#define THREADS 128
#define K_PAD 72                     // halves per row; 144B stride

#define A_BYTES (M_TILE * K_PAD * 2)   // 18432
#define B_BYTES (N_TILE * K_PAD * 2)   // 9216
#define SM_A0 0
#define SM_B0 (SM_A0 + A_BYTES)
#define SM_A1 (SM_B0 + B_BYTES)
#define SM_B1 (SM_A1 + A_BYTES)
#define SMEM_BYTES (SM_B1 + B_BYTES)   // 55296  -> 4 CTAs/SM

// prepass grid split
#define NB_NORM 2048
#define NB_X    512

// ---------------- device scratch ----------------
__device__ uint32_t g_cn2[G_TOT];        // half2(2n/3, -n) per group
__device__ __half   g_xh[M_TOT * K_TOT]; // x in fp16

__device__ __forceinline__ uint32_t smem_u32(const void* p) {
    uint32_t a;
    asm("{ .reg .u64 t; cvta.to.shared.u64 t, %1; cvt.u32.u64 %0, t; }" : "=r"(a) : "l"(p));
    return a;
}
#define CP_ASYNC16(dst, src) \
    asm volatile("cp.async.cg.shared.global [%0], [%1], 16;" :: "r"(dst), "l"(src) : "memory")
#define CP_COMMIT() asm volatile("cp.async.commit_group;" ::: "memory")
#define CP_WAIT0()  asm volatile("cp.async.wait_group 0;" ::: "memory")
#define LDSM_X4(r0, r1, r2, r3, a) \
    asm volatile("ldmatrix.sync.aligned.m8n8.x4.shared.b16 {%0,%1,%2,%3}, [%4];" \
        : "=r"(r0), "=r"(r1), "=r"(r2), "=r"(r3) : "r"(a))
#define MMAF32(acc, a0, a1, a2, a3, b0, b1)                                    \
    asm volatile("mma.sync.aligned.m16n8k16.row.col.f32.f16.f16.f32 "          \
        "{%0,%1,%2,%3}, {%4,%5,%6,%7}, {%8,%9}, {%0,%1,%2,%3};\n"              \
        : "+f"((acc)[0]), "+f"((acc)[1]), "+f"((acc)[2]), "+f"((acc)[3])       \
        : "r"(a0), "r"(a1), "r"(a2), "r"(a3), "r"(b0), "r"(b1))

// ---------------- fused prepass ----------------
__global__ void prepass(const uint16_t* __restrict__ pnorm,
                        const float* __restrict__ x)
{
    const int tid = threadIdx.x;
    const int b = blockIdx.x;
    if (b < NB_NORM) {
        const int base = (b * 256 + tid) * 8;
        uint4 raw = *(const uint4*)(pnorm + base);
        uint16_t h[8];
        *(uint4*)h = raw;
        float vh[8], vb[8];
        bool okh = true, okb = true, bigh = false, bigb = false;
#pragma unroll
        for (int i = 0; i < 8; i++) {
            vh[i] = __half2float(*(const __half*)&h[i]);
            vb[i] = __bfloat162float(*(const __nv_bfloat16*)&h[i]);
            okh &= (vh[i] > 1e-6f && vh[i] < 1.0f);
            okb &= (vb[i] > 1e-6f && vb[i] < 1.0f);
            bigh |= (vh[i] > 0.1f);
            bigb |= (vb[i] > 0.1f);
        }
        int allh = __syncthreads_and(okh);
        int allb = __syncthreads_and(okb);
        int anyh = __syncthreads_or(okh && bigh);
        int anyb = __syncthreads_or(okb && bigb);
        uint32_t outw[8];
        if (allh && anyh) {
#pragma unroll
            for (int i = 0; i < 8; i++) {
                __half2 o = __halves2half2(__float2half_rn(vh[i] * (2.0f / 3.0f)),
                                           __float2half_rn(-vh[i]));
                outw[i] = *(uint32_t*)&o;
            }
        } else if (allb && anyb) {
#pragma unroll
            for (int i = 0; i < 8; i++) {
                __half2 o = __halves2half2(__float2half_rn(vb[i] * (2.0f / 3.0f)),
                                           __float2half_rn(-vb[i]));
                outw[i] = *(uint32_t*)&o;
            }
        } else {
            const float* pf = (const float*)pnorm;
#pragma unroll
            for (int i = 0; i < 8; i++) {
                float v = pf[base + i];
                __half2 o = __halves2half2(__float2half_rn(v * (2.0f / 3.0f)),
                                           __float2half_rn(-v));
                outw[i] = *(uint32_t*)&o;
            }
        }
        uint32_t* dst = g_cn2 + base;
        *(uint4*)(dst)     = make_uint4(outw[0], outw[1], outw[2], outw[3]);
        *(uint4*)(dst + 4) = make_uint4(outw[4], outw[5], outw[6], outw[7]);
    } else {
        const int base = ((b - NB_NORM) * 256 + tid) * 8;
        float4 v0 = *(const float4*)(x + base);
        float4 v1 = *(const float4*)(x + base + 4);
        __half2 o[4];
        o[0] = __floats2half2_rn(v0.x, v0.y);
        o[1] = __floats2half2_rn(v0.z, v0.w);
        o[2] = __floats2half2_rn(v1.x, v1.y);
        o[3] = __floats2half2_rn(v1.z, v1.w);
        *(uint4*)(g_xh + base) = *(uint4*)o;
    }
}

// dequant one group's 4 packed words into 8 half2 words
__device__ __forceinline__ void dequant_group(const int4 q, uint32_t n2,
                                              uint32_t hv[8])
{
    const uint32_t MAGIC = 0x64006400u;
    const __half2  magic_h2 = *(const __half2*)&MAGIC;
    __half2 cn = *(__half2*)&n2;
    __half2 tc2 = __half2half2(__low2half(cn));    // 2n/3
    __half2 m32 = __half2half2(__high2half(cn));   // -n
    int words[4] = {q.x, q.y, q.z, q.w};
#pragma unroll
    for (int w = 0; w < 4; w++) {
        uint32_t qq = (uint32_t)words[w];
        uint32_t u01 = MAGIC | (qq & 3u) | ((qq & 0xCu) << 14);
        uint32_t u23 = MAGIC | ((qq >> 4) & 3u) | ((qq & 0xC0u) << 10);
        __half2 v01 = __hsub2(*(__half2*)&u01, magic_h2);
        __half2 v23 = __hsub2(*(__half2*)&u23, magic_h2);
        __half2 w01 = __hfma2(v01, tc2, m32);
        __half2 w23 = __hfma2(v23, tc2, m32);
        hv[w * 2]     = *(uint32_t*)&w01;
        hv[w * 2 + 1] = *(uint32_t*)&w23;
    }
}

// ---------------- main GEMM: 128 thr, tile 128x64, 4 CTAs/SM ----------------
__global__ __launch_bounds__(THREADS, 4)
void l2b_hmma(const int4* __restrict__ wq,
              const uint32_t* __restrict__ cn2,
              const __half* __restrict__ xh,
              const float* __restrict__ bias,
              float* __restrict__ out)
{
    extern __shared__ char smem[];
    const uint32_t sb = smem_u32(smem);
    const int tid  = threadIdx.x;
    const int lane = tid & 31;
    const int warp = tid >> 5;        // 0..3 : 32 M rows each; all N
    const int noff = blockIdx.x * N_TILE;
    const int moff = blockIdx.y * M_TILE;

    // warp tile 32M x 64N: acc[2 mfrag][8 nfrag][4]
    float acc[2][8][4];
#pragma unroll
    for (int i = 0; i < 2; i++)
#pragma unroll
        for (int j = 0; j < 8; j++)
#pragma unroll
            for (int r = 0; r < 4; r++) acc[i][j][r] = 0.f;

    int4     qr[2];
    uint32_t nr[2];
    uint32_t hv0[8];       // pre-dequanted group 0 for current chunk

    // group ids: gl = tid + h*128; wn = gl>>2 (0..63), wgi = gl&3
    const int wn0  = tid >> 2, wgi0 = tid & 3;
    const int wn1  = (tid + 128) >> 2, wgi1 = tid & 3;

    // A staging: 1024 16B segs, 8 per thread
    auto issueA = [&](int c, uint32_t abase) {
#pragma unroll
        for (int h = 0; h < 8; h++) {
            int seg = tid + h * 128;
            int row = seg >> 3;
            int s   = seg & 7;
            const __half* src = xh + (size_t)(moff + row) * K_TOT + c * K_CHUNK + s * 8;
            uint32_t dst = abase + row * (K_PAD * 2) + s * 16;
            CP_ASYNC16(dst, src);
        }
        CP_COMMIT();
    };
    auto loadW = [&](int c) {
        int g0 = (noff + wn0) * GPR + c * 4 + wgi0;
        int g1 = (noff + wn1) * GPR + c * 4 + wgi1;
        qr[0] = wq[g0];  nr[0] = cn2[g0];
        qr[1] = wq[g1];  nr[1] = cn2[g1];
    };

    issueA(0, sb + SM_A0);
    loadW(0);
    dequant_group(qr[0], nr[0], hv0);   // group 0, chunk 0

    uint32_t aoff[2];
#pragma unroll
    for (int mi = 0; mi < 2; mi++)
        aoff[mi] = (uint32_t)(warp * 32 + mi * 16 + (lane & 15)) * (K_PAD * 2)
                 + ((lane >> 4) & 1) * 16;
    uint32_t boff[4];
#pragma unroll
    for (int np = 0; np < 4; np++)
        boff[np] = (uint32_t)(np * 16 + ((lane & 7) | ((lane & 16) >> 1))) * (K_PAD * 2)
                 + ((lane >> 3) & 1) * 16;

    const uint32_t st0 = (uint32_t)wn0 * (K_PAD * 2) + wgi0 * 32;
    const uint32_t st1 = (uint32_t)wn1 * (K_PAD * 2) + wgi1 * 32;

    for (int c = 0; c < NCHUNK; ++c) {
        const int pb = c & 1;
        const uint32_t abase = sb + (pb ? SM_A1 : SM_A0);
        const uint32_t bbase = sb + (pb ? SM_B1 : SM_B0);

        // ---- STS group 0 (pre-dequanted), dequant+STS group 1
        asm volatile("st.shared.v4.b32 [%0], {%1,%2,%3,%4};"
            :: "r"(bbase + st0), "r"(hv0[0]), "r"(hv0[1]), "r"(hv0[2]), "r"(hv0[3]) : "memory");
        asm volatile("st.shared.v4.b32 [%0], {%1,%2,%3,%4};"
            :: "r"(bbase + st0 + 16), "r"(hv0[4]), "r"(hv0[5]), "r"(hv0[6]), "r"(hv0[7]) : "memory");
        {
            uint32_t hv1[8];
            dequant_group(qr[1], nr[1], hv1);
            asm volatile("st.shared.v4.b32 [%0], {%1,%2,%3,%4};"
                :: "r"(bbase + st1), "r"(hv1[0]), "r"(hv1[1]), "r"(hv1[2]), "r"(hv1[3]) : "memory");
            asm volatile("st.shared.v4.b32 [%0], {%1,%2,%3,%4};"
                :: "r"(bbase + st1 + 16), "r"(hv1[4]), "r"(hv1[5]), "r"(hv1[6]), "r"(hv1[7]) : "memory");
        }

        CP_WAIT0();
        __syncthreads();

        if (c + 1 < NCHUNK) {
            issueA(c + 1, sb + (pb ? SM_A0 : SM_A1));
            loadW(c + 1);   // arrives during compute below
        }

        // ---- compute chunk c
#pragma unroll
        for (int ks = 0; ks < 4; ++ks) {
            const uint32_t kb = ks * 32;
            uint32_t a0, a1, a2, a3, a4, a5, a6, a7;
            LDSM_X4(a0, a1, a2, a3, abase + aoff[0] + kb);
            LDSM_X4(a4, a5, a6, a7, abase + aoff[1] + kb);
#pragma unroll
            for (int np = 0; np < 4; np++) {
                uint32_t b0, b1, b2, b3;
                LDSM_X4(b0, b1, b2, b3, bbase + boff[np] + kb);
#pragma unroll
                for (int e = 0; e < 2; e++) {
                    int ni = np * 2 + e;
                    uint32_t bb0 = e ? b2 : b0;
                    uint32_t bb1 = e ? b3 : b1;
                    MMAF32(acc[0][ni], a0, a1, a2, a3, bb0, bb1);
                    MMAF32(acc[1][ni], a4, a5, a6, a7, bb0, bb1);
                }
            }
        }

        // ---- pre-dequant group 0 for next chunk (qr[0] loaded above, long arrived)
        if (c + 1 < NCHUNK)
            dequant_group(qr[0], nr[0], hv0);
    }

    // ---- epilogue: bias + fp32 store
#pragma unroll
    for (int mi = 0; mi < 2; mi++) {
        int r = moff + warp * 32 + mi * 16 + (lane >> 2);
#pragma unroll
        for (int ni = 0; ni < 8; ni++) {
            int ncol = noff + ni * 8 + (lane & 3) * 2;
            float b0 = bias[ncol];
            float b1 = bias[ncol + 1];
            float2* o0 = (float2*)(out + (size_t)r * N_TOT + ncol);
            float2* o1 = (float2*)(out + (size_t)(r + 8) * N_TOT + ncol);
            *o0 = make_float2(acc[mi][ni][0] + b0, acc[mi][ni][1] + b1);
            *o1 = make_float2(acc[mi][ni][2] + b0, acc[mi][ni][3] + b1);
        }
    }
}

// ---------------- launcher ----------------
extern "C" void kernel_launch(void* const* d_in, const int* in_sizes, int n_in,
                              void* d_out, int out_size)
{
    // Bind by size order: wq > norm > x > bias
    int order[4] = {0, 1, 2, 3};
    for (int i = 1; i < 4 && i < n_in; i++) {
        int v = order[i], j = i - 1;
        while (j >= 0 && (long long)in_sizes[order[j]] < (long long)in_sizes[v]) {
            order[j + 1] = order[j]; j--;
        }
        order[j + 1] = v;
    }
    const int4*     wq    = (const int4*)d_in[order[0]];
    const uint16_t* pnorm = (const uint16_t*)d_in[order[1]];
    const float*    x     = (const float*)d_in[order[2]];
    const float*    bias  = (const float*)d_in[order[3]];
    float* out = (float*)d_out;

    prepass<<<NB_NORM + NB_X, 256>>>(pnorm, x);

    uint32_t* cn2_dev = nullptr;
    __half*   xh_dev  = nullptr;
    cudaGetSymbolAddress((void**)&cn2_dev, g_cn2);
    cudaGetSymbolAddress((void**)&xh_dev, g_xh);

    cudaFuncSetAttribute(l2b_hmma, cudaFuncAttributeMaxDynamicSharedMemorySize, SMEM_BYTES);
    dim3 grid(N_TOT / N_TILE, M_TOT / M_TILE);   // (256, 2) = 512 CTAs, 4/SM
    l2b_hmma<<<grid, THREADS, SMEM_BYTES>>>(wq, cn2_dev, xh_dev, bias, out);
}

// round 9
// speedup vs baseline: 1.0747x; 1.0747x over previous
#include <cuda_runtime.h>
#include <cuda_fp16.h>
#include <cuda_bf16.h>
#include <cstdint>

#define M_TOT 256
#define N_TOT 16384
#define K_TOT 4096
#define GPR   (K_TOT / 16)           // 256 groups per row

#define M_TILE 128
#define N_TILE 128
#define K_CHUNK 64
#define NCHUNK (K_TOT / K_CHUNK)     // 64
#define THREADS 256
#define K_PAD 72                     // halves per row; 144B stride

#define A_BYTES (M_TILE * K_PAD * 2)   // 18432
#define B_BYTES (N_TILE * K_PAD * 2)   // 18432
#define SM_A0 0
#define SM_B0 (SM_A0 + A_BYTES)
#define SM_A1 (SM_B0 + B_BYTES)
#define SM_B1 (SM_A1 + A_BYTES)
#define SMEM_BYTES (SM_B1 + B_BYTES)   // 73728 -> 2 CTAs/SM

#define NB_X 512    // x-convert blocks: 512*256*8 = 1048576 floats

// ---------------- device scratch ----------------
__device__ __half g_xh[M_TOT * K_TOT]; // x in fp16 (2 MB)
__device__ int    g_norm_dtype;        // 0=fp16, 1=bf16, 2=fp32

__device__ __forceinline__ uint32_t smem_u32(const void* p) {
    uint32_t a;
    asm("{ .reg .u64 t; cvta.to.shared.u64 t, %1; cvt.u32.u64 %0, t; }" : "=r"(a) : "l"(p));
    return a;
}
#define CP_ASYNC16(dst, src) \
    asm volatile("cp.async.cg.shared.global [%0], [%1], 16;" :: "r"(dst), "l"(src) : "memory")
#define CP_COMMIT() asm volatile("cp.async.commit_group;" ::: "memory")
#define CP_WAIT0()  asm volatile("cp.async.wait_group 0;" ::: "memory")
#define LDSM_X4(r0, r1, r2, r3, a) \
    asm volatile("ldmatrix.sync.aligned.m8n8.x4.shared.b16 {%0,%1,%2,%3}, [%4];" \
        : "=r"(r0), "=r"(r1), "=r"(r2), "=r"(r3) : "r"(a))
#define MMAF32(acc, a0, a1, a2, a3, b0, b1)                                    \
    asm volatile("mma.sync.aligned.m16n8k16.row.col.f32.f16.f16.f32 "          \
        "{%0,%1,%2,%3}, {%4,%5,%6,%7}, {%8,%9}, {%0,%1,%2,%3};\n"              \
        : "+f"((acc)[0]), "+f"((acc)[1]), "+f"((acc)[2]), "+f"((acc)[3])       \
        : "r"(a0), "r"(a1), "r"(a2), "r"(a3), "r"(b0), "r"(b1))

// ---------------- prepass: x fp32->fp16 + norm dtype detect ----------------
__global__ void prepass(const uint16_t* __restrict__ pnorm,
                        const float* __restrict__ x)
{
    const int tid = threadIdx.x;
    const int b = blockIdx.x;

    if (b == 0 && tid < 32) {
        bool okh = true, okb = true, bigh = false, bigb = false;
#pragma unroll
        for (int i = 0; i < 8; i++) {
            uint16_t r = pnorm[tid * 8 + i];
            float vh = __half2float(*(const __half*)&r);
            float vb = __bfloat162float(*(const __nv_bfloat16*)&r);
            okh &= (vh > 1e-6f && vh < 1.0f);
            okb &= (vb > 1e-6f && vb < 1.0f);
            bigh |= (vh > 0.1f);
            bigb |= (vb > 0.1f);
        }
        bool allh = __all_sync(0xffffffffu, okh);
        bool allb = __all_sync(0xffffffffu, okb);
        bool anyh = __any_sync(0xffffffffu, bigh);
        bool anyb = __any_sync(0xffffffffu, bigb);
        if (tid == 0)
            g_norm_dtype = (allh && anyh) ? 0 : ((allb && anyb) ? 1 : 2);
    }

    const int base = (b * 256 + tid) * 8;
    float4 v0 = *(const float4*)(x + base);
    float4 v1 = *(const float4*)(x + base + 4);
    __half2 o[4];
    o[0] = __floats2half2_rn(v0.x, v0.y);
    o[1] = __floats2half2_rn(v0.z, v0.w);
    o[2] = __floats2half2_rn(v1.x, v1.y);
    o[3] = __floats2half2_rn(v1.z, v1.w);
    *(uint4*)(g_xh + base) = *(uint4*)o;
}

// dequant one group's 4 packed words into 8 half2 words; nf = norm in fp32
__device__ __forceinline__ void dequant_group(const int4 q, float nf,
                                              uint32_t hv[8])
{
    const uint32_t MAGIC = 0x64006400u;
    const __half2  magic_h2 = *(const __half2*)&MAGIC;
    __half2 tc2 = __half2half2(__float2half_rn(nf * (2.0f / 3.0f)));
    __half2 m32 = __half2half2(__float2half_rn(-nf));
    int words[4] = {q.x, q.y, q.z, q.w};
#pragma unroll
    for (int w = 0; w < 4; w++) {
        uint32_t qq = (uint32_t)words[w];
        uint32_t u01 = MAGIC | (qq & 3u) | ((qq & 0xCu) << 14);
        uint32_t u23 = MAGIC | ((qq >> 4) & 3u) | ((qq & 0xC0u) << 10);
        __half2 v01 = __hsub2(*(__half2*)&u01, magic_h2);
        __half2 v23 = __hsub2(*(__half2*)&u23, magic_h2);
        __half2 w01 = __hfma2(v01, tc2, m32);
        __half2 w23 = __hfma2(v23, tc2, m32);
        hv[w * 2]     = *(uint32_t*)&w01;
        hv[w * 2 + 1] = *(uint32_t*)&w23;
    }
}

// ---------------- main GEMM: 256 thr, tile 128x128, 2 CTAs/SM ----------------
__global__ __launch_bounds__(THREADS, 2)
void l2b_hmma(const int4* __restrict__ wq,
              const uint16_t* __restrict__ pnorm,
              const __half* __restrict__ xh,
              const float* __restrict__ bias,
              float* __restrict__ out)
{
    extern __shared__ char smem[];
    const uint32_t sb = smem_u32(smem);
    const int tid  = threadIdx.x;
    const int lane = tid & 31;
    const int warp = tid >> 5;
    const int warp_m = warp >> 2;     // 0..1 : 64 M rows each
    const int warp_n = warp & 3;      // 0..3 : 32 N cols each
    const int noff = blockIdx.x * N_TILE;
    const int moff = blockIdx.y * M_TILE;
    const int dt = g_norm_dtype;

    float acc[4][4][4];
#pragma unroll
    for (int i = 0; i < 4; i++)
#pragma unroll
        for (int j = 0; j < 4; j++)
#pragma unroll
            for (int r = 0; r < 4; r++) acc[i][j][r] = 0.f;

    int4     qr[2];
    uint32_t nr[2];    // raw norm bits (16-bit pattern or f32 bits)

    auto issueA = [&](int c, uint32_t abase) {
#pragma unroll
        for (int h = 0; h < 4; h++) {
            int seg = tid + h * 256;
            int row = seg >> 3;
            int s   = seg & 7;
            const __half* src = xh + (size_t)(moff + row) * K_TOT + c * K_CHUNK + s * 8;
            uint32_t dst = abase + row * (K_PAD * 2) + s * 16;
            CP_ASYNC16(dst, src);
        }
        CP_COMMIT();
    };
    auto loadW = [&](int c) {
#pragma unroll
        for (int h = 0; h < 2; h++) {
            int gl  = tid + h * 256;
            int wn  = gl >> 2;
            int wgi = gl & 3;
            int g   = (noff + wn) * GPR + c * 4 + wgi;
            qr[h] = wq[g];
            if (dt == 2) nr[h] = ((const uint32_t*)pnorm)[g];
            else         nr[h] = pnorm[g];
        }
    };
    auto rawToF = [&](uint32_t r) -> float {
        if (dt == 0)      return __half2float(__ushort_as_half((unsigned short)r));
        else if (dt == 1) return __uint_as_float(r << 16);
        else              return __uint_as_float(r);
    };

    issueA(0, sb + SM_A0);
    loadW(0);

    uint32_t aoff[4];
#pragma unroll
    for (int mi = 0; mi < 4; mi++)
        aoff[mi] = (uint32_t)(warp_m * 64 + mi * 16 + (lane & 15)) * (K_PAD * 2)
                 + ((lane >> 4) & 1) * 16;
    uint32_t boff[2];
#pragma unroll
    for (int np = 0; np < 2; np++)
        boff[np] = (uint32_t)(warp_n * 32 + np * 16 + ((lane & 7) | ((lane & 16) >> 1))) * (K_PAD * 2)
                 + ((lane >> 3) & 1) * 16;

    for (int c = 0; c < NCHUNK; ++c) {
        const int pb = c & 1;
        const uint32_t abase = sb + (pb ? SM_A1 : SM_A0);
        const uint32_t bbase = sb + (pb ? SM_B1 : SM_B0);

        // ---- dequant + STS B(c)
#pragma unroll
        for (int h = 0; h < 2; h++) {
            int gl  = tid + h * 256;
            int wn  = gl >> 2;
            int wgi = gl & 3;
            uint32_t hv[8];
            dequant_group(qr[h], rawToF(nr[h]), hv);
            uint32_t a0 = bbase + (uint32_t)wn * (K_PAD * 2) + wgi * 32;
            asm volatile("st.shared.v4.b32 [%0], {%1,%2,%3,%4};"
                :: "r"(a0), "r"(hv[0]), "r"(hv[1]), "r"(hv[2]), "r"(hv[3]) : "memory");
            asm volatile("st.shared.v4.b32 [%0], {%1,%2,%3,%4};"
                :: "r"(a0 + 16), "r"(hv[4]), "r"(hv[5]), "r"(hv[6]), "r"(hv[7]) : "memory");
        }

        CP_WAIT0();
        __syncthreads();

        if (c + 1 < NCHUNK) {
            issueA(c + 1, sb + (pb ? SM_A0 : SM_A1));
            loadW(c + 1);
        }

        // ---- compute chunk c with B-fragment double buffering
        {
            uint32_t af[4][4];
            uint32_t bf[2][4];
            LDSM_X4(bf[0][0], bf[0][1], bf[0][2], bf[0][3], bbase + boff[0]);  // ks0 np0
#pragma unroll
            for (int ks = 0; ks < 4; ++ks) {
                const uint32_t kb = ks * 32;
#pragma unroll
                for (int mi = 0; mi < 4; mi++)
                    LDSM_X4(af[mi][0], af[mi][1], af[mi][2], af[mi][3],
                            abase + aoff[mi] + kb);
                // np = 0: prefetch np=1, compute with bf[0]
                LDSM_X4(bf[1][0], bf[1][1], bf[1][2], bf[1][3], bbase + boff[1] + kb);
#pragma unroll
                for (int e = 0; e < 2; e++) {
                    uint32_t bb0 = e ? bf[0][2] : bf[0][0];
                    uint32_t bb1 = e ? bf[0][3] : bf[0][1];
#pragma unroll
                    for (int mi = 0; mi < 4; mi++)
                        MMAF32(acc[mi][e], af[mi][0], af[mi][1], af[mi][2], af[mi][3],
                               bb0, bb1);
                }
                // np = 1: prefetch next ks np=0, compute with bf[1]
                if (ks < 3)
                    LDSM_X4(bf[0][0], bf[0][1], bf[0][2], bf[0][3],
                            bbase + boff[0] + kb + 32);
#pragma unroll
                for (int e = 0; e < 2; e++) {
                    uint32_t bb0 = e ? bf[1][2] : bf[1][0];
                    uint32_t bb1 = e ? bf[1][3] : bf[1][1];
#pragma unroll
                    for (int mi = 0; mi < 4; mi++)
                        MMAF32(acc[mi][2 + e], af[mi][0], af[mi][1], af[mi][2], af[mi][3],
                               bb0, bb1);
                }
            }
        }
    }

    // ---- epilogue: bias + fp32 store
#pragma unroll
    for (int mi = 0; mi < 4; mi++) {
        int r = moff + warp_m * 64 + mi * 16 + (lane >> 2);
#pragma unroll
        for (int ni = 0; ni < 4; ni++) {
            int ncol = noff + warp_n * 32 + ni * 8 + (lane & 3) * 2;
            float b0 = bias[ncol];
            float b1 = bias[ncol + 1];
            float2* o0 = (float2*)(out + (size_t)r * N_TOT + ncol);
            float2* o1 = (float2*)(out + (size_t)(r + 8) * N_TOT + ncol);
            *o0 = make_float2(acc[mi][ni][0] + b0, acc[mi][ni][1] + b1);
            *o1 = make_float2(acc[mi][ni][2] + b0, acc[mi][ni][3] + b1);
        }
    }
}

// ---------------- launcher ----------------
extern "C" void kernel_launch(void* const* d_in, const int* in_sizes, int n_in,
                              void* d_out, int out_size)
{
    // Bind by size order: wq > norm > x > bias
    int order[4] = {0, 1, 2, 3};
    for (int i = 1; i < 4 && i < n_in; i++) {
        int v = order[i], j = i - 1;
        while (j >= 0 && (long long)in_sizes[order[j]] < (long long)in_sizes[v]) {
            order[j + 1] = order[j]; j--;
        }
        order[j + 1] = v;
    }
    const int4*     wq    = (const int4*)d_in[order[0]];
    const uint16_t* pnorm = (const uint16_t*)d_in[order[1]];
    const float*    x     = (const float*)d_in[order[2]];
    const float*    bias  = (const float*)d_in[order[3]];
    float* out = (float*)d_out;

    prepass<<<NB_X, 256>>>(pnorm, x);

    __half* xh_dev = nullptr;
    cudaGetSymbolAddress((void**)&xh_dev, g_xh);

    cudaFuncSetAttribute(l2b_hmma, cudaFuncAttributeMaxDynamicSharedMemorySize, SMEM_BYTES);
    dim3 grid(N_TOT / N_TILE, M_TOT / M_TILE);   // (128, 2) = 256 CTAs, 2/SM
    l2b_hmma<<<grid, THREADS, SMEM_BYTES>>>(wq, pnorm, xh_dev, bias, out);
}